// round 6
// baseline (speedup 1.0000x reference)
#include <cuda_runtime.h>
#include <cuda_fp16.h>
#include <math.h>
#include <stdint.h>

#define NN 50000
#define NE 800000
#define FI 128
#define FH 256
#define K1 25000
#define K2 12500
#define NSCAN 49  // ceil(NN/1024)

// ---------------- scratch (device globals; zero-init, allocation-free) -----
__device__ __align__(16) float g_xa[NN * FH];    // L5 gemm out
__device__ __align__(16) float g_h[NN * FH];     // L0 gemm out
__device__ __align__(16) float g_hid0[NN * FH];  // L1 out (full)
__device__ __align__(16) float g_hid1[NN * FH];  // L2 out (scattered; else 0)
__device__ __align__(16) float g_hbot[NN * FH];  // L3 out (scattered; else 0)
__device__ __align__(16) float g_h4[NN * FH];    // L4 out (scattered; else 0)
__device__ __align__(16) __half g_xh[NN * FH];   // gemm A hi
__device__ __align__(16) __half g_xl[NN * FH];   // gemm A lo
__device__ __align__(16) __half g_wth[327680];   // weights hi (transposed)
__device__ __align__(16) __half g_wtl[327680];   // weights lo
__device__ int g_degout[NN];
__device__ int g_degO1[NN], g_degI1[NN], g_degO2[NN], g_degI2[NN];
__device__ float g_comb1[NN], g_dov1[NN], g_div1[NN];
__device__ float g_comb2[NN], g_dov2[NN], g_div2[NN];
__device__ float g_scores[NN];
__device__ unsigned g_keys[NN];
__device__ int g_rowstart[NN + 1];
__device__ int g_rowoff[NN];
__device__ int g_csrsrc[NE];
__device__ int g_alist1[NN], g_alist2[NN];
__device__ int g_nact[2];
__device__ unsigned g_prefix;
__device__ int g_bsum[64];

#define WO_EMB  0
#define WO_ENC0 32768
#define WO_ENC1 98304
#define WO_BOT  163840
#define WO_DEC0 229376
#define WO_DEC1 294912

__device__ __forceinline__ unsigned f2k(float f) {
    unsigned u = __float_as_uint(f);
    return (u & 0x80000000u) ? ~u : (u | 0x80000000u);
}
__device__ __forceinline__ void split4(float4 v, __half2* ph, __half2* pl) {
    __half h0 = __float2half_rn(v.x), h1 = __float2half_rn(v.y);
    __half h2 = __float2half_rn(v.z), h3 = __float2half_rn(v.w);
    __half l0 = __float2half_rn(v.x - __half2float(h0));
    __half l1 = __float2half_rn(v.y - __half2float(h1));
    __half l2 = __float2half_rn(v.z - __half2float(h2));
    __half l3 = __float2half_rn(v.w - __half2float(h3));
    ph[0] = __halves2half2(h0, h1); ph[1] = __halves2half2(h2, h3);
    pl[0] = __halves2half2(l0, l1); pl[1] = __halves2half2(l2, l3);
}

// ---------------- prep: zero counters + transpose+split all weights --------
__global__ void prep_kernel(const float* __restrict__ We, const float* __restrict__ W0,
                            const float* __restrict__ W1, const float* __restrict__ Wb,
                            const float* __restrict__ Wd0, const float* __restrict__ Wd1) {
    int i = blockIdx.x * blockDim.x + threadIdx.x;
    if (i < NN) {
        g_rowoff[i] = 0; g_degout[i] = 0;
        g_degO1[i] = 0; g_degI1[i] = 0;
        g_degO2[i] = 0; g_degI2[i] = 0;
    }
    if (i == 0) { g_nact[0] = 0; g_nact[1] = 0; g_rowstart[NN] = NE; }
    float w; int o;
    if (i < 32768) {                       // embed: K=128,N=256
        int k = i >> 8, n = i & 255;
        w = We[i]; o = WO_EMB + n * 128 + k;
    } else if (i < 98304) {
        int j = i - 32768; int k = j >> 8, n = j & 255;
        w = W0[j]; o = WO_ENC0 + n * 256 + k;
    } else if (i < 163840) {
        int j = i - 98304; int k = j >> 8, n = j & 255;
        w = W1[j]; o = WO_ENC1 + n * 256 + k;
    } else if (i < 229376) {
        int j = i - 163840; int k = j >> 8, n = j & 255;
        w = Wb[j]; o = WO_BOT + n * 256 + k;
    } else if (i < 294912) {
        int j = i - 229376; int k = j >> 8, n = j & 255;
        w = Wd0[j]; o = WO_DEC0 + n * 256 + k;
    } else if (i < 327680) {               // dec1: K=256,N=128
        int j = i - 294912; int k = j >> 7, n = j & 127;
        w = Wd1[j]; o = WO_DEC1 + n * 256 + k;
    } else return;
    __half h = __float2half_rn(w);
    g_wth[o] = h;
    g_wtl[o] = __float2half_rn(w - __half2float(h));
}

// ---------------- CSR build ----------------
__global__ void hist_kernel(const int* __restrict__ src, const int* __restrict__ dst) {
    int e = blockIdx.x * blockDim.x + threadIdx.x;
    if (e < NE) {
        atomicAdd(&g_rowoff[dst[e]], 1);
        atomicAdd(&g_degout[src[e]], 1);
    }
}
__global__ void scan1_kernel() {
    int b = blockIdx.x, t = threadIdx.x;
    int i = b * 1024 + t;
    int v = (i < NN) ? g_rowoff[i] : 0;
    int lane = t & 31, wid = t >> 5;
    int x = v;
#pragma unroll
    for (int off = 1; off < 32; off <<= 1) {
        int y = __shfl_up_sync(0xFFFFFFFFu, x, off);
        if (lane >= off) x += y;
    }
    __shared__ int ws[32];
    if (lane == 31) ws[wid] = x;
    __syncthreads();
    if (wid == 0) {
        int y = ws[lane];
#pragma unroll
        for (int off = 1; off < 32; off <<= 1) {
            int z = __shfl_up_sync(0xFFFFFFFFu, y, off);
            if (lane >= off) y += z;
        }
        ws[lane] = y;
    }
    __syncthreads();
    int base = wid ? ws[wid - 1] : 0;
    if (i < NN) g_rowstart[i] = base + x - v;
    if (t == 1023) g_bsum[b] = base + x;
}
// scan3: per-block prefix of the 49 partials in smem, then offset-add.
__global__ void scan3_kernel() {
    __shared__ int boff[NSCAN + 1];
    int t = threadIdx.x;
    if (t < NSCAN) boff[t + 1] = g_bsum[t];
    __syncthreads();
    if (t == 0) {
        boff[0] = 0;
        for (int b = 1; b <= NSCAN; b++) boff[b] += boff[b - 1];
    }
    __syncthreads();
    int i = blockIdx.x * blockDim.x + t;
    if (i < NN) {
        int rs = g_rowstart[i] + boff[i >> 10];
        g_rowstart[i] = rs;
        g_rowoff[i] = rs;
    }
}
__global__ void scatter_kernel(const int* __restrict__ src, const int* __restrict__ dst) {
    int e = blockIdx.x * blockDim.x + threadIdx.x;
    if (e < NE) {
        int pos = atomicAdd(&g_rowoff[dst[e]], 1);
        g_csrsrc[pos] = src[e];
    }
}

// ---------------- CSR aggregation: 1 warp per node, shfl edge staging ------
// out = (sum_src (x+x2)[src]*sc(src)) * div(node) -> fp16 hi/lo split
__global__ void agg_half_kernel(const float* __restrict__ x, const float* __restrict__ x2,
                                const float* __restrict__ smul, const int* __restrict__ degsrc,
                                const float* __restrict__ divv, const int* __restrict__ alist,
                                __half* __restrict__ oh, __half* __restrict__ ol,
                                int F, int nnodes) {
    int wid = (blockIdx.x * blockDim.x + threadIdx.x) >> 5;
    if (wid >= nnodes) return;
    int lane = threadIdx.x & 31;
    int node = alist ? alist[wid] : wid;
    int s = g_rowstart[node], e = g_rowstart[node + 1];
    int f4 = F >> 2;
    bool wide = (f4 == 64);
    float4 a0 = make_float4(0.f, 0.f, 0.f, 0.f);
    float4 a1 = make_float4(0.f, 0.f, 0.f, 0.f);
    for (int b = s; b < e; b += 32) {
        int nn = min(32, e - b);
        int si = 0; float sc = 0.f;
        if (lane < nn) {
            si = g_csrsrc[b + lane];
            if (smul) sc = smul[si];
            else if (degsrc) sc = rsqrtf((float)max(degsrc[si], 1));
            else sc = 1.f;
        }
        for (int k = 0; k < nn; k++) {
            int sik = __shfl_sync(0xFFFFFFFFu, si, k);
            float sck = __shfl_sync(0xFFFFFFFFu, sc, k);
            if (sck != 0.f) {
                const float4* xp = (const float4*)x + (size_t)sik * f4 + lane;
                float4 v = xp[0];
                if (x2) {
                    float4 w = ((const float4*)x2)[(size_t)sik * f4 + lane];
                    v.x += w.x; v.y += w.y; v.z += w.z; v.w += w.w;
                }
                a0.x = fmaf(v.x, sck, a0.x); a0.y = fmaf(v.y, sck, a0.y);
                a0.z = fmaf(v.z, sck, a0.z); a0.w = fmaf(v.w, sck, a0.w);
                if (wide) {
                    float4 v1 = xp[32];
                    if (x2) {
                        float4 w1 = ((const float4*)x2)[(size_t)sik * f4 + lane + 32];
                        v1.x += w1.x; v1.y += w1.y; v1.z += w1.z; v1.w += w1.w;
                    }
                    a1.x = fmaf(v1.x, sck, a1.x); a1.y = fmaf(v1.y, sck, a1.y);
                    a1.z = fmaf(v1.z, sck, a1.z); a1.w = fmaf(v1.w, sck, a1.w);
                }
            }
        }
    }
    float dv = divv ? divv[node] : rsqrtf((float)max(e - s, 1));
    a0.x *= dv; a0.y *= dv; a0.z *= dv; a0.w *= dv;
    int wrow = alist ? wid : node;
    size_t o = (size_t)wrow * F + lane * 4;
    split4(a0, (__half2*)(oh + o), (__half2*)(ol + o));
    if (wide) {
        a1.x *= dv; a1.y *= dv; a1.z *= dv; a1.w *= dv;
        split4(a1, (__half2*)(oh + o + 128), (__half2*)(ol + o + 128));
    }
}

// final layer: fp32 out + bias, unit edge scale, inline divs (F=128)
__global__ void agg_out_kernel(const float* __restrict__ x, const float* __restrict__ bias,
                               float* __restrict__ out) {
    int wid = (blockIdx.x * blockDim.x + threadIdx.x) >> 5;
    if (wid >= NN) return;
    int lane = threadIdx.x & 31;
    int s = g_rowstart[wid], e = g_rowstart[wid + 1];
    float4 acc = make_float4(0.f, 0.f, 0.f, 0.f);
    for (int b = s; b < e; b += 32) {
        int nn = min(32, e - b);
        int si = 0;
        if (lane < nn) si = g_csrsrc[b + lane];
        for (int k = 0; k < nn; k++) {
            int sik = __shfl_sync(0xFFFFFFFFu, si, k);
            float4 v = ((const float4*)x)[(size_t)sik * 32 + lane];
            acc.x += v.x; acc.y += v.y; acc.z += v.z; acc.w += v.w;
        }
    }
    float dv = rsqrtf((float)max(e - s, 1));
    float4 bb = ((const float4*)bias)[lane];
    acc.x = fmaf(acc.x, dv, bb.x); acc.y = fmaf(acc.y, dv, bb.y);
    acc.z = fmaf(acc.z, dv, bb.z); acc.w = fmaf(acc.w, dv, bb.w);
    ((float4*)out)[(size_t)wid * 32 + lane] = acc;
}

// ---------------- HMMA fp16-split GEMM ----------------
#define SMS 72
#define GEMM_SMEM (4 * 128 * SMS * 2)

#define MMA168(d, a, b) \
    asm volatile( \
        "mma.sync.aligned.m16n8k16.row.col.f32.f16.f16.f32 " \
        "{%0,%1,%2,%3}, {%4,%5,%6,%7}, {%8,%9}, {%0,%1,%2,%3};" \
        : "+f"((d)[0]), "+f"((d)[1]), "+f"((d)[2]), "+f"((d)[3]) \
        : "r"((a)[0]), "r"((a)[1]), "r"((a)[2]), "r"((a)[3]), \
          "r"((b)[0]), "r"((b)[1]))

template <int AHALF>
__global__ void __launch_bounds__(256, 2)
gemm_kernel(const __half* __restrict__ Ah, const __half* __restrict__ Al,
            const float* __restrict__ A0, const float* __restrict__ A1,
            const __half* __restrict__ Bh, const __half* __restrict__ Bl,
            float* __restrict__ C, int M, int K, int N,
            const int* __restrict__ alist, const float* __restrict__ bias,
            const int* __restrict__ degrm, int act) {
    extern __shared__ __half sm[];
    __half* sAh = sm;
    __half* sAl = sAh + 128 * SMS;
    __half* sBh = sAl + 128 * SMS;
    __half* sBl = sBh + 128 * SMS;
    int t = threadIdx.x;
    int m0 = blockIdx.y * 128, n0 = blockIdx.x * 128;
    int w = t >> 5, lane = t & 31;
    int g = lane >> 2, tig = lane & 3;
    int wm = (w & 1) * 64, wn = (w >> 1) * 32;

    float acc[4][4][4];
#pragma unroll
    for (int i = 0; i < 4; i++)
#pragma unroll
        for (int j = 0; j < 4; j++)
#pragma unroll
            for (int k = 0; k < 4; k++) acc[i][j][k] = 0.f;

    for (int kc = 0; kc < K; kc += 64) {
        if (AHALF) {
            for (int idx = t; idx < 2048; idx += 256) {
                int arr = idx >> 10, j = idx & 1023, r = j >> 3, c = j & 7;
                const __half* srcp = arr ? Al : Ah;
                uint4 v = make_uint4(0, 0, 0, 0);
                if (m0 + r < M) v = *(const uint4*)(srcp + (size_t)(m0 + r) * K + kc + c * 8);
                *(uint4*)((arr ? sAl : sAh) + r * SMS + c * 8) = v;
            }
        } else {
            for (int idx = t; idx < 1024; idx += 256) {
                int r = idx >> 3, c = idx & 7;
                float4 f0 = make_float4(0.f, 0.f, 0.f, 0.f), f1 = f0;
                if (m0 + r < M) {
                    size_t o = (size_t)(m0 + r) * K + kc + c * 8;
                    f0 = *(const float4*)(A0 + o);
                    f1 = *(const float4*)(A0 + o + 4);
                    float4 q0 = *(const float4*)(A1 + o);
                    float4 q1 = *(const float4*)(A1 + o + 4);
                    f0.x += q0.x; f0.y += q0.y; f0.z += q0.z; f0.w += q0.w;
                    f1.x += q1.x; f1.y += q1.y; f1.z += q1.z; f1.w += q1.w;
                }
                split4(f0, (__half2*)(sAh + r * SMS + c * 8), (__half2*)(sAl + r * SMS + c * 8));
                split4(f1, (__half2*)(sAh + r * SMS + c * 8 + 4), (__half2*)(sAl + r * SMS + c * 8 + 4));
            }
        }
        for (int idx = t; idx < 2048; idx += 256) {
            int arr = idx >> 10, j = idx & 1023, r = j >> 3, c = j & 7;
            const __half* srcp = arr ? Bl : Bh;
            uint4 v = *(const uint4*)(srcp + (size_t)(n0 + r) * K + kc + c * 8);
            *(uint4*)((arr ? sBl : sBh) + r * SMS + c * 8) = v;
        }
        __syncthreads();
#pragma unroll
        for (int ks = 0; ks < 4; ks++) {
            int kb = ks * 16 + tig * 2;
            uint32_t ar[4][4], br[4][2], br2[4][2];
#pragma unroll
            for (int mi = 0; mi < 4; mi++) {
                int r = wm + mi * 16 + g;
                ar[mi][0] = *(const uint32_t*)(sAh + r * SMS + kb);
                ar[mi][1] = *(const uint32_t*)(sAh + (r + 8) * SMS + kb);
                ar[mi][2] = *(const uint32_t*)(sAh + r * SMS + kb + 8);
                ar[mi][3] = *(const uint32_t*)(sAh + (r + 8) * SMS + kb + 8);
            }
#pragma unroll
            for (int ni = 0; ni < 4; ni++) {
                int r = wn + ni * 8 + g;
                br[ni][0]  = *(const uint32_t*)(sBh + r * SMS + kb);
                br[ni][1]  = *(const uint32_t*)(sBh + r * SMS + kb + 8);
                br2[ni][0] = *(const uint32_t*)(sBl + r * SMS + kb);
                br2[ni][1] = *(const uint32_t*)(sBl + r * SMS + kb + 8);
            }
#pragma unroll
            for (int mi = 0; mi < 4; mi++)
#pragma unroll
                for (int ni = 0; ni < 4; ni++) {
                    MMA168(acc[mi][ni], ar[mi], br[ni]);
                    MMA168(acc[mi][ni], ar[mi], br2[ni]);
                }
#pragma unroll
            for (int mi = 0; mi < 4; mi++) {
                int r = wm + mi * 16 + g;
                ar[mi][0] = *(const uint32_t*)(sAl + r * SMS + kb);
                ar[mi][1] = *(const uint32_t*)(sAl + (r + 8) * SMS + kb);
                ar[mi][2] = *(const uint32_t*)(sAl + r * SMS + kb + 8);
                ar[mi][3] = *(const uint32_t*)(sAl + (r + 8) * SMS + kb + 8);
            }
#pragma unroll
            for (int mi = 0; mi < 4; mi++)
#pragma unroll
                for (int ni = 0; ni < 4; ni++)
                    MMA168(acc[mi][ni], ar[mi], br[ni]);
        }
        __syncthreads();
    }

#pragma unroll
    for (int mi = 0; mi < 4; mi++) {
#pragma unroll
        for (int half8 = 0; half8 < 2; half8++) {
            int lrow = m0 + wm + mi * 16 + g + half8 * 8;
            if (lrow >= M) continue;
            int grow = alist ? alist[lrow] : lrow;
            float rm = degrm ? rsqrtf((float)max(degrm[grow], 1)) : 1.f;
#pragma unroll
            for (int ni = 0; ni < 4; ni++) {
                int col = n0 + wn + ni * 8 + tig * 2;
                float v0 = acc[mi][ni][half8 * 2 + 0];
                float v1 = acc[mi][ni][half8 * 2 + 1];
                if (bias) { v0 += bias[col]; v1 += bias[col + 1]; }
                if (act) { v0 = fmaxf(v0, 0.f); v1 = fmaxf(v1, 0.f); }
                v0 *= rm; v1 *= rm;
                *(float2*)(C + (size_t)grow * N + col) = make_float2(v0, v1);
            }
        }
    }
}

// ---------------- pooling ----------------
__global__ void scores_kernel(const float* __restrict__ h, const float* __restrict__ Wp,
                              const float* __restrict__ bp, const float* __restrict__ msk) {
    int warp = (blockIdx.x * blockDim.x + threadIdx.x) >> 5;
    int lane = threadIdx.x & 31;
    if (warp >= NN) return;
    const float* hr = h + (size_t)warp * FH;
    float z = 0.f;
#pragma unroll
    for (int j = 0; j < 8; j++) z = fmaf(hr[lane + 32 * j], Wp[lane + 32 * j], z);
#pragma unroll
    for (int off = 16; off; off >>= 1) z += __shfl_xor_sync(0xFFFFFFFFu, z, off);
    if (lane == 0) {
        z += bp[0];
        float s = 1.f / (1.f + expf(-z));
        g_scores[warp] = s;
        float kin = (msk && msk[warp] == 0.f) ? -1e9f : s;
        g_keys[warp] = f2k(kin);
    }
}

__global__ void topk_kernel(int K, int lvl) {
    __shared__ int hist[256];
    __shared__ unsigned s_pref;
    __shared__ int s_kr;
    int tid = threadIdx.x;
    if (tid == 0) { s_pref = 0u; s_kr = K; }
    const int NPAD = ((NN + 1023) / 1024) * 1024;
    for (int shift = 24; shift >= 0; shift -= 8) {
        if (tid < 256) hist[tid] = 0;
        __syncthreads();
        unsigned pref = s_pref;
        for (int i = tid; i < NPAD; i += 1024) {
            unsigned bucket = 0xFFFFFFFFu;
            if (i < NN) {
                unsigned k = g_keys[i];
                bool ok = (shift == 24) || ((k >> (shift + 8)) == (pref >> (shift + 8)));
                if (ok) bucket = (k >> shift) & 255u;
            }
            unsigned peers = __match_any_sync(0xFFFFFFFFu, bucket);
            if (bucket != 0xFFFFFFFFu) {
                int leader = __ffs(peers) - 1;
                if ((tid & 31) == leader) atomicAdd(&hist[bucket], __popc(peers));
            }
        }
        __syncthreads();
        if (tid == 0) {
            int kr = s_kr;
            for (int b = 255; b >= 0; b--) {
                int c = hist[b];
                if (c >= kr) { s_pref = pref | (((unsigned)b) << shift); break; }
                kr -= c;
            }
            s_kr = kr;
        }
        __syncthreads();
    }
    if (tid == 0) { g_prefix = s_pref; g_nact[lvl] = 0; }
}

__global__ void degm_kernel(const int* __restrict__ src, const int* __restrict__ dst,
                            int* __restrict__ degO, int* __restrict__ degI) {
    int e = blockIdx.x * blockDim.x + threadIdx.x;
    if (e >= NE) return;
    int s = src[e], d = dst[e];
    if (g_keys[s] >= g_prefix && g_keys[d] >= g_prefix) {
        atomicAdd(&degO[s], 1);
        atomicAdd(&degI[d], 1);
    }
}

// fused buildact + fin
__global__ void finact_kernel(const int* __restrict__ degO, const int* __restrict__ degI,
                              float* __restrict__ comb, float* __restrict__ dov,
                              float* __restrict__ divv, int* __restrict__ alist, int lvl) {
    int i = blockIdx.x * blockDim.x + threadIdx.x;
    if (i >= NN) return;
    float mo = rsqrtf((float)max(degO[i], 1));
    bool a = g_keys[i] >= g_prefix;
    comb[i] = a ? g_scores[i] * mo : 0.f;
    dov[i] = a ? mo : 0.f;
    divv[i] = rsqrtf((float)max(degI[i], 1));
    if (a) {
        int p = atomicAdd(&g_nact[lvl], 1);
        alist[p] = i;
    }
}

// ---------------- host orchestration ----------------
static inline void* sym(const void* s) {
    void* p = nullptr;
    cudaGetSymbolAddress(&p, (const void*)s);
    return p;
}

extern "C" void kernel_launch(void* const* d_in, const int* in_sizes, int n_in,
                              void* d_out, int out_size) {
    const float* features = (const float*)d_in[0];
    const int* src = (const int*)d_in[1];
    const int* dst = (const int*)d_in[2];
    const float* W_embed = (const float*)d_in[3];
    const float* b_embed = (const float*)d_in[4];
    const float* W_enc0 = (const float*)d_in[5];
    const float* b_enc0 = (const float*)d_in[6];
    const float* W_enc1 = (const float*)d_in[7];
    const float* b_enc1 = (const float*)d_in[8];
    const float* W_p0 = (const float*)d_in[9];
    const float* b_p0 = (const float*)d_in[10];
    const float* W_p1 = (const float*)d_in[11];
    const float* b_p1 = (const float*)d_in[12];
    const float* W_bot = (const float*)d_in[13];
    const float* b_bot = (const float*)d_in[14];
    const float* W_dec0 = (const float*)d_in[15];
    const float* b_dec0 = (const float*)d_in[16];
    const float* W_dec1 = (const float*)d_in[17];
    const float* b_dec1 = (const float*)d_in[18];
    float* out = (float*)d_out;

    float* p_xa   = (float*)sym(g_xa);
    float* p_h    = (float*)sym(g_h);
    float* p_hid0 = (float*)sym(g_hid0);
    float* p_hid1 = (float*)sym(g_hid1);
    float* p_hbot = (float*)sym(g_hbot);
    float* p_h4   = (float*)sym(g_h4);
    __half* p_xh  = (__half*)sym(g_xh);
    __half* p_xl  = (__half*)sym(g_xl);
    __half* p_wth = (__half*)sym(g_wth);
    __half* p_wtl = (__half*)sym(g_wtl);
    int* p_degout = (int*)sym(g_degout);
    int* p_degO1  = (int*)sym(g_degO1);
    int* p_degI1  = (int*)sym(g_degI1);
    int* p_degO2  = (int*)sym(g_degO2);
    int* p_degI2  = (int*)sym(g_degI2);
    float* p_comb1 = (float*)sym(g_comb1);
    float* p_dov1  = (float*)sym(g_dov1);
    float* p_div1  = (float*)sym(g_div1);
    float* p_comb2 = (float*)sym(g_comb2);
    float* p_dov2  = (float*)sym(g_dov2);
    float* p_div2  = (float*)sym(g_div2);
    int* p_al1 = (int*)sym(g_alist1);
    int* p_al2 = (int*)sym(g_alist2);

    cudaFuncSetAttribute(gemm_kernel<1>, cudaFuncAttributeMaxDynamicSharedMemorySize, GEMM_SMEM);
    cudaFuncSetAttribute(gemm_kernel<0>, cudaFuncAttributeMaxDynamicSharedMemorySize, GEMM_SMEM);

    const int TB = 256;
    const int NB_N = (NN + TB - 1) / TB;
    const int NB_E = (NE + TB - 1) / TB;
    dim3 gFull256(2, (NN + 127) / 128);
    dim3 gFull128(1, (NN + 127) / 128);
    dim3 gK1(2, (K1 + 127) / 128);
    dim3 gK2(2, (K2 + 127) / 128);
    auto wgrid = [](int n) { return (n + 7) / 8; };  // 8 warps per 256-thread block

    // prep + CSR build
    prep_kernel<<<(327680 + TB - 1) / TB, TB>>>(W_embed, W_enc0, W_enc1, W_bot, W_dec0, W_dec1);
    hist_kernel<<<NB_E, TB>>>(src, dst);
    scan1_kernel<<<NSCAN, 1024>>>();
    scan3_kernel<<<NB_N, TB>>>();
    scatter_kernel<<<NB_E, TB>>>(src, dst);

    // L0
    agg_half_kernel<<<wgrid(NN), TB>>>(features, nullptr, nullptr, p_degout, nullptr, nullptr,
                                       p_xh, p_xl, FI, NN);
    gemm_kernel<1><<<gFull256, 256, GEMM_SMEM>>>(p_xh, p_xl, nullptr, nullptr,
                                                 p_wth + WO_EMB, p_wtl + WO_EMB, p_h,
                                                 NN, FI, FH, nullptr, b_embed, nullptr, 1);

    // L1
    agg_half_kernel<<<wgrid(NN), TB>>>(p_h, nullptr, nullptr, p_degout, nullptr, nullptr,
                                       p_xh, p_xl, FH, NN);
    gemm_kernel<1><<<gFull256, 256, GEMM_SMEM>>>(p_xh, p_xl, nullptr, nullptr,
                                                 p_wth + WO_ENC0, p_wtl + WO_ENC0, p_hid0,
                                                 NN, FH, FH, nullptr, b_enc0, nullptr, 1);

    // pool0
    scores_kernel<<<(NN + 7) / 8, TB>>>(p_hid0, W_p0, b_p0, nullptr);
    topk_kernel<<<1, 1024>>>(K1, 0);
    degm_kernel<<<NB_E, TB>>>(src, dst, p_degO1, p_degI1);
    finact_kernel<<<NB_N, TB>>>(p_degO1, p_degI1, p_comb1, p_dov1, p_div1, p_al1, 0);

    // L2
    agg_half_kernel<<<wgrid(K1), TB>>>(p_hid0, nullptr, p_comb1, nullptr, p_div1, p_al1,
                                       p_xh, p_xl, FH, K1);
    gemm_kernel<1><<<gK1, 256, GEMM_SMEM>>>(p_xh, p_xl, nullptr, nullptr,
                                            p_wth + WO_ENC1, p_wtl + WO_ENC1, p_hid1,
                                            K1, FH, FH, p_al1, b_enc1, nullptr, 1);

    // pool1
    scores_kernel<<<(NN + 7) / 8, TB>>>(p_hid1, W_p1, b_p1, p_dov1);
    topk_kernel<<<1, 1024>>>(K2, 1);
    degm_kernel<<<NB_E, TB>>>(src, dst, p_degO2, p_degI2);
    finact_kernel<<<NB_N, TB>>>(p_degO2, p_degI2, p_comb2, p_dov2, p_div2, p_al2, 1);

    // L3
    agg_half_kernel<<<wgrid(K2), TB>>>(p_hid1, nullptr, p_comb2, nullptr, p_div2, p_al2,
                                       p_xh, p_xl, FH, K2);
    gemm_kernel<1><<<gK2, 256, GEMM_SMEM>>>(p_xh, p_xl, nullptr, nullptr,
                                            p_wth + WO_BOT, p_wtl + WO_BOT, p_hbot,
                                            K2, FH, FH, p_al2, b_bot, nullptr, 1);

    // L4 (skip add fused in agg)
    agg_half_kernel<<<wgrid(K1), TB>>>(p_hbot, p_hid1, p_dov1, nullptr, p_div1, p_al1,
                                       p_xh, p_xl, FH, K1);
    gemm_kernel<1><<<gK1, 256, GEMM_SMEM>>>(p_xh, p_xl, nullptr, nullptr,
                                            p_wth + WO_DEC0, p_wtl + WO_DEC0, p_h4,
                                            K1, FH, FH, p_al1, b_dec0, nullptr, 1);

    // L5: GEMM first with fused (h4+hid0); then agg + bias -> out
    gemm_kernel<0><<<gFull128, 256, GEMM_SMEM>>>(nullptr, nullptr, p_h4, p_hid0,
                                                 p_wth + WO_DEC1, p_wtl + WO_DEC1, p_xa,
                                                 NN, FH, FI, nullptr, nullptr, p_degout, 0);
    agg_out_kernel<<<wgrid(NN), TB>>>(p_xa, b_dec1, out);
}